// round 6
// baseline (speedup 1.0000x reference)
#include <cuda_runtime.h>

// Fixed shapes
#define NB 4096
#define NS 200
#define XST 212   // XsT row stride in floats (float4-aligned rows)

// smem offsets (bytes), all 16B-aligned
#define OFF_MS    0        // 64*64 floats, plain row-major          (16384)
#define OFF_W2S   16384    // 64*32 floats, per-row chunk XOR swizzle (8192)
#define OFF_CS    24576    // 64 floats  layer-1 bias c_b            (256)
#define OFF_B2S   24832    // 32 floats                              (128)
#define OFF_W3S   24960    // 32 floats                              (128)
#define OFF_BNSC  25088    // 128 floats                             (512)
#define OFF_BNSH  25600    // 128 floats                             (512)
#define OFF_QS    26112    // 64 floats                              (256)
#define OFF_LG    26368    // 200 floats                             (800)
#define OFF_WE    27168    // 200 floats (16B aligned)               (800)
#define OFF_RED   27968    // red[0]=max red[1]=1/sum red[2]=b3      (16)
#define OFF_XST   27984    // 64*212 floats + 48 pad                 (54464)
#define SMEM_BYTES 82448

typedef unsigned long long u64;

__device__ __forceinline__ u64 pack2(float a, float b) {
    u64 r;
    asm("mov.b64 %0, {%1, %2};" : "=l"(r)
        : "r"(__float_as_uint(a)), "r"(__float_as_uint(b)));
    return r;
}
__device__ __forceinline__ void ffma2(u64& d, u64 a, u64 b) {
    asm("fma.rn.f32x2 %0, %1, %2, %0;" : "+l"(d) : "l"(a), "l"(b));
}
__device__ __forceinline__ void add2(u64& d, u64 a) {
    asm("add.rn.f32x2 %0, %0, %1;" : "+l"(d) : "l"(a));
}
__device__ __forceinline__ float lo32(u64 v) { return __uint_as_float((unsigned)v); }
__device__ __forceinline__ float hi32(u64 v) { return __uint_as_float((unsigned)(v >> 32)); }
__device__ __forceinline__ u64 shflx64(u64 v, int m, unsigned msk) {
    double d = __longlong_as_double((long long)v);
    d = __shfl_xor_sync(msk, d, m);
    return (u64)__double_as_longlong(d);
}

extern __shared__ unsigned char smem_raw[];

__global__ void __launch_bounds__(256, 2) din_user_rep_kernel(
    const float* __restrict__ em,   const float* __restrict__ eu,
    const float* __restrict__ Xu,   const float* __restrict__ W1,
    const float* __restrict__ b1,   const float* __restrict__ W2,
    const float* __restrict__ b2,   const float* __restrict__ W3,
    const float* __restrict__ b3,   const float* __restrict__ gamma,
    const float* __restrict__ beta, const float* __restrict__ mmean,
    const float* __restrict__ mvar, float* __restrict__ out)
{
    const int t = threadIdx.x;
    const int b = blockIdx.x;

    float* Ms   = (float*)(smem_raw + OFF_MS);
    float* W2s  = (float*)(smem_raw + OFF_W2S);
    float* cs   = (float*)(smem_raw + OFF_CS);
    float* b2s  = (float*)(smem_raw + OFF_B2S);
    float* w3s  = (float*)(smem_raw + OFF_W3S);
    float* bnsc = (float*)(smem_raw + OFF_BNSC);
    float* bnsh = (float*)(smem_raw + OFF_BNSH);
    float* qs   = (float*)(smem_raw + OFF_QS);
    float* lg   = (float*)(smem_raw + OFF_LG);
    float* we   = (float*)(smem_raw + OFF_WE);
    float* red  = (float*)(smem_raw + OFF_RED);
    float* XsT  = (float*)(smem_raw + OFF_XST);

    // ---- Phase 0: per-batch vectors + parameter staging ----
    if (t < 64)  qs[t] = em[(size_t)b * 64 + t];
    if (t < 128) {
        float sc = gamma[t] * rsqrtf(mvar[t] + 1e-3f);
        bnsc[t] = sc;
        bnsh[t] = beta[t] - mmean[t] * sc;
    }
    if (t < 32) { w3s[t] = W3[t]; b2s[t] = b2[t]; }
    if (t == 0) red[2] = b3[0];

    // W2 -> smem, per-row chunk XOR swizzle: chunk (j>>2) stored at slot
    // (j>>2) ^ ((k>>2)&7). Layer-2 lane ct reads row k with (k>>2)&7 == ct,
    // so the 8 lanes' 16B loads land in 8 distinct bank quads.
    for (int e = t; e < 2048; e += 256) {
        int k = e >> 5, j = e & 31;
        W2s[k * 32 + (((j >> 2) ^ ((k >> 2) & 7)) << 2) + (j & 3)] = W2[e];
    }

    // Xu transpose staging (coalesced global sub-rows -> contiguous STS.128)
    const float* Xb = Xu + (size_t)b * (NS * 64);
    for (int e = t; e < 64 * 50; e += 256) {
        int d = e & 63, sc = e >> 6;
        float x0 = Xb[(4 * sc + 0) * 64 + d];
        float x1 = Xb[(4 * sc + 1) * 64 + d];
        float x2 = Xb[(4 * sc + 2) * 64 + d];
        float x3 = Xb[(4 * sc + 3) * 64 + d];
        *(float4*)(XsT + d * XST + 4 * sc) = make_float4(x0, x1, x2, x3);
    }
    __syncthreads();   // qs ready for folds

    // ---- Phase 1: folded layer-1 weights (plain row-major) ----
    for (int e = t; e < 4096; e += 256) {
        int k = e >> 6, c = e & 63;
        Ms[e] = W1[(64 + k) * 64 + c] - W1[(128 + k) * 64 + c]
              + qs[k] * W1[(192 + k) * 64 + c];
    }
    if (t < 64) {
        float c0 = b1[t];
        for (int k = 0; k < 64; k++)
            c0 += qs[k] * (W1[k * 64 + t] + W1[(128 + k) * 64 + t]);
        cs[t] = c0;
    }
    __syncthreads();

    // ---- Phase 2: 8x8 register-tiled MLP ----
    // rt = t>>3 (0..24), ct = t&7. Lane owns rows 8rt..8rt+7 and cols
    // {4ct..4ct+3} U {32+4ct..35+4ct}  (acc pairs p0..p3 in that order).
    if (t < 200) {
        const int rt = t >> 3, ct = t & 7;
        const int s0 = 8 * rt;
        const unsigned gmask = 0xFFu << ((t & 31) & 24);

        u64 acc[8][4];
        {
            ulonglong2 ci0 = *(const ulonglong2*)(cs + 4 * ct);
            ulonglong2 ci1 = *(const ulonglong2*)(cs + 32 + 4 * ct);
            #pragma unroll
            for (int r = 0; r < 8; r++) {
                acc[r][0] = ci0.x; acc[r][1] = ci0.y;
                acc[r][2] = ci1.x; acc[r][3] = ci1.y;
            }
        }
        const float* xp = XsT + s0;
        const float* mp = Ms + 4 * ct;

        #pragma unroll 4
        for (int k = 0; k < 64; k++) {
            float4 xa = *(const float4*)(xp + k * XST);
            float4 xb = *(const float4*)(xp + k * XST + 4);
            ulonglong2 m0 = *(const ulonglong2*)(mp + k * 64);
            ulonglong2 m1 = *(const ulonglong2*)(mp + k * 64 + 32);
            u64 xx[8] = { pack2(xa.x, xa.x), pack2(xa.y, xa.y),
                          pack2(xa.z, xa.z), pack2(xa.w, xa.w),
                          pack2(xb.x, xb.x), pack2(xb.y, xb.y),
                          pack2(xb.z, xb.z), pack2(xb.w, xb.w) };
            #pragma unroll
            for (int r = 0; r < 8; r++) {
                ffma2(acc[r][0], xx[r], m0.x);
                ffma2(acc[r][1], xx[r], m0.y);
                ffma2(acc[r][2], xx[r], m1.x);
                ffma2(acc[r][3], xx[r], m1.y);
            }
        }

        // relu(h1) in place (once, keeps ALU off the critical path in layer 2)
        #pragma unroll
        for (int r = 0; r < 8; r++)
            #pragma unroll
            for (int p = 0; p < 4; p++)
                acc[r][p] = pack2(fmaxf(lo32(acc[r][p]), 0.f),
                                  fmaxf(hi32(acc[r][p]), 0.f));

        // Layer 2+3: lane's 8 k-rows = {4ct+i} and {32+4ct+i}; j-chunks of 4;
        // 3-round shfl butterfly over the 8-lane ct group completes h2.
        float lacc[8] = {0, 0, 0, 0, 0, 0, 0, 0};
        #pragma unroll 1
        for (int jc = 0; jc < 8; jc++) {
            u64 hb[8][2];
            #pragma unroll
            for (int r = 0; r < 8; r++) { hb[r][0] = 0ull; hb[r][1] = 0ull; }

            const int wofs = (jc ^ ct) << 2;
            #pragma unroll
            for (int i = 0; i < 8; i++) {
                int k = (i < 4) ? (4 * ct + i) : (28 + 4 * ct + i);
                ulonglong2 w = *(const ulonglong2*)(W2s + k * 32 + wofs);
                #pragma unroll
                for (int r = 0; r < 8; r++) {
                    float hv = (i & 1) ? hi32(acc[r][i >> 1])
                                       : lo32(acc[r][i >> 1]);
                    u64 hh = pack2(hv, hv);
                    ffma2(hb[r][0], hh, w.x);
                    ffma2(hb[r][1], hh, w.y);
                }
            }
            #pragma unroll
            for (int r = 0; r < 8; r++)
                #pragma unroll
                for (int p = 0; p < 2; p++) {
                    add2(hb[r][p], shflx64(hb[r][p], 1, gmask));
                    add2(hb[r][p], shflx64(hb[r][p], 2, gmask));
                    add2(hb[r][p], shflx64(hb[r][p], 4, gmask));
                }
            ulonglong2 b2v = *(const ulonglong2*)(b2s + 4 * jc);
            ulonglong2 w3v = *(const ulonglong2*)(w3s + 4 * jc);
            float w30 = lo32(w3v.x), w31 = hi32(w3v.x);
            float w32 = lo32(w3v.y), w33 = hi32(w3v.y);
            #pragma unroll
            for (int r = 0; r < 8; r++) {
                u64 h0 = hb[r][0]; add2(h0, b2v.x);
                u64 h1v = hb[r][1]; add2(h1v, b2v.y);
                lacc[r] += fmaxf(lo32(h0), 0.f) * w30
                         + fmaxf(hi32(h0), 0.f) * w31
                         + fmaxf(lo32(h1v), 0.f) * w32
                         + fmaxf(hi32(h1v), 0.f) * w33;
            }
        }
        if (ct == 0) {
            float b3v = red[2];
            #pragma unroll
            for (int r = 0; r < 8; r++) lg[s0 + r] = lacc[r] + b3v;
        }
    }
    __syncthreads();

    // ---- Softmax reduction (warp 0) ----
    if (t < 32) {
        float m = -3.0e38f;
        for (int r = t; r < NS; r += 32) m = fmaxf(m, lg[r]);
        #pragma unroll
        for (int o = 16; o; o >>= 1) m = fmaxf(m, __shfl_xor_sync(0xffffffffu, m, o));
        float ssum = 0.f;
        for (int r = t; r < NS; r += 32) ssum += __expf(lg[r] - m);
        #pragma unroll
        for (int o = 16; o; o >>= 1) ssum += __shfl_xor_sync(0xffffffffu, ssum, o);
        if (t == 0) { red[0] = m; red[1] = 1.f / ssum; }
    }
    __syncthreads();
    if (t < NS) we[t] = __expf(lg[t] - red[0]) * red[1];
    __syncthreads();

    // ---- Pool + BN + output: out row = [bn(pooled), bn(em), eu] ----
    float* ob = out + (size_t)b * 192;
    if (t < 64) {
        const float4* xr = (const float4*)(XsT + t * XST);
        const float4* wv = (const float4*)we;
        float p = 0.f;
        #pragma unroll 5
        for (int sc = 0; sc < 50; sc++) {
            float4 x = xr[sc], w = wv[sc];
            p += x.x * w.x + x.y * w.y + x.z * w.z + x.w * w.w;
        }
        ob[t] = p * bnsc[t] + bnsh[t];
    } else if (t < 128) {
        ob[t] = qs[t - 64] * bnsc[t] + bnsh[t];
    } else if (t < 192) {
        ob[t] = eu[(size_t)b * 64 + (t - 128)];
    }
}

extern "C" void kernel_launch(void* const* d_in, const int* in_sizes, int n_in,
                              void* d_out, int out_size) {
    (void)in_sizes; (void)n_in; (void)out_size;
    cudaFuncSetAttribute(din_user_rep_kernel,
                         cudaFuncAttributeMaxDynamicSharedMemorySize, SMEM_BYTES);
    din_user_rep_kernel<<<NB, 256, SMEM_BYTES>>>(
        (const float*)d_in[0],  // em
        (const float*)d_in[1],  // eu
        (const float*)d_in[2],  // Xu
        (const float*)d_in[3],  // W1
        (const float*)d_in[4],  // b1
        (const float*)d_in[5],  // W2
        (const float*)d_in[6],  // b2
        (const float*)d_in[7],  // W3
        (const float*)d_in[8],  // b3
        (const float*)d_in[9],  // gamma
        (const float*)d_in[10], // beta
        (const float*)d_in[11], // mov_mean
        (const float*)d_in[12], // mov_var
        (float*)d_out);
}